// round 13
// baseline (speedup 1.0000x reference)
#include <cuda_runtime.h>
#include <cuda_bf16.h>

// VideoEmbedding: out[n, d] = sum_k W[vid[n], d, k] * basis(t[n])[k]
// K = 13, D = 32, V = 32, N = 1048576.
//
// Round 12 (resubmit; broker timeouts ate rounds 8-11's benches).
// Sort-by-vid design with the round-8 deadlock fix: hist/scatter warp loops
// use warp-uniform loop bounds (wbase), so __ballot/__match collectives are
// never executed by partially-exited warps.
//   Kernels: transpose(+init) -> hist -> scan -> scatter -> main (persistent).

#define EMB_V 32
#define EMB_D 32
#define EMB_F 6
#define EMB_K 13
#define NMAX (1 << 21)

#define MAIN_GRID 444
#define MAIN_THREADS 512
#define MAIN_WARPS (MAIN_THREADS / 32)

#define HIST_GRID 296
#define SC_BLOCKS 1024

// Weights: [V][D][16] floats, quad-swizzled: logical quad j of row (v,d) is
// stored at physical quad j ^ ((d>>1)&3). 64KB.
__device__ float g_wt[EMB_V * EMB_D * 16];
// Sorted (time_bits, vid<<26|orig_idx) pairs.
__device__ uint2 g_spair[NMAX];
__device__ int g_total[EMB_V];
__device__ int g_cursor[EMB_V];

__global__ void transpose_weights_kernel(const float* __restrict__ w) {
    // Fused init: zero the histogram (stream order makes this visible to hist).
    if (blockIdx.x == 0 && threadIdx.x < EMB_V) g_total[threadIdx.x] = 0;

    int i = blockIdx.x * blockDim.x + threadIdx.x;  // dst word index
    if (i >= EMB_V * EMB_D * 16) return;
    int v = i >> 9;
    int d = (i >> 4) & 31;
    int p = (i >> 2) & 3;       // physical quad
    int c = i & 3;
    int j = p ^ ((d >> 1) & 3); // logical quad
    int k = j * 4 + c;
    g_wt[i] = (k < EMB_K) ? w[v * (EMB_D * EMB_K) + d * EMB_K + k] : 0.0f;
}

__global__ void hist_kernel(const int* __restrict__ vids, int n) {
    __shared__ int sh[EMB_V];
    if (threadIdx.x < EMB_V) sh[threadIdx.x] = 0;
    __syncthreads();
    int lane = threadIdx.x & 31;
    int stride = gridDim.x * blockDim.x;
    // Warp-uniform loop bound: wbase is lane-invariant.
    for (int wbase = blockIdx.x * blockDim.x + (threadIdx.x & ~31); wbase < n;
         wbase += stride) {
        int i = wbase + lane;
        bool valid = (i < n);
        unsigned am = __ballot_sync(0xffffffffu, valid);
        if (valid) {
            int v = vids[i];
            unsigned m = __match_any_sync(am, v);
            int leader = __ffs(m) - 1;
            if (lane == leader) atomicAdd(&sh[v], __popc(m));
        }
    }
    __syncthreads();
    if (threadIdx.x < EMB_V) atomicAdd(&g_total[threadIdx.x], sh[threadIdx.x]);
}

__global__ void scan_kernel() {
    int v = threadIdx.x;
    int c = g_total[v];
    int x = c;
#pragma unroll
    for (int o = 1; o < 32; o <<= 1) {
        int y = __shfl_up_sync(0xffffffffu, x, o);
        if (v >= o) x += y;
    }
    g_cursor[v] = x - c;  // exclusive prefix
}

__global__ void scatter_kernel(const float* __restrict__ times,
                               const int* __restrict__ vids, int n) {
    __shared__ int sh[EMB_V];
    __shared__ int run[EMB_V];
    int chunk = (n + SC_BLOCKS - 1) / SC_BLOCKS;
    int cs = blockIdx.x * chunk;
    int ce = min(n, cs + chunk);
    if (threadIdx.x < EMB_V) sh[threadIdx.x] = 0;
    __syncthreads();
    int lane = threadIdx.x & 31;

    // Pass A: local histogram (warp-aggregated); warp-uniform loop bound.
    for (int wbase = cs + (threadIdx.x & ~31); wbase < ce; wbase += blockDim.x) {
        int i = wbase + lane;
        bool valid = (i < ce);
        unsigned am = __ballot_sync(0xffffffffu, valid);
        if (valid) {
            int v = vids[i];
            unsigned m = __match_any_sync(am, v);
            if (lane == __ffs(m) - 1) atomicAdd(&sh[v], __popc(m));
        }
    }
    __syncthreads();
    // Pass B: reserve global segments.
    if (threadIdx.x < EMB_V)
        run[threadIdx.x] = atomicAdd(&g_cursor[threadIdx.x], sh[threadIdx.x]);
    __syncthreads();
    // Pass C: place rays; warp-uniform loop bound.
    for (int wbase = cs + (threadIdx.x & ~31); wbase < ce; wbase += blockDim.x) {
        int i = wbase + lane;
        bool valid = (i < ce);
        unsigned am = __ballot_sync(0xffffffffu, valid);
        if (valid) {
            int v = vids[i];
            float t = times[i];
            unsigned m = __match_any_sync(am, v);
            int leader = __ffs(m) - 1;
            int rank = __popc(m & ((1u << lane) - 1));
            int base = 0;
            if (lane == leader) base = atomicAdd(&run[v], __popc(m));
            base = __shfl_sync(m, base, leader);
            g_spair[base + rank] =
                make_uint2(__float_as_uint(t), ((unsigned)v << 26) | (unsigned)i);
        }
    }
}

__global__ void __launch_bounds__(MAIN_THREADS)
main_kernel(float* __restrict__ out, int n) {
    // Per-warp basis staging: [32 rays][16 floats], quad-swizzled.
    __shared__ float sbasis[MAIN_WARPS][32 * 16];

    int lane = threadIdx.x & 31;
    int wid = threadIdx.x >> 5;
    float* sb = sbasis[wid];

    // Contiguous sorted range for this warp.
    int warps_total = MAIN_GRID * MAIN_WARPS;
    int rpw = ((n + warps_total - 1) / warps_total + 31) & ~31;
    int g = blockIdx.x * MAIN_WARPS + wid;
    int wstart = g * rpw;
    int wend = min(n, wstart + rpw);
    if (wstart >= wend) return;

    const int sl = (lane >> 1) & 3;  // this lane's weight quad swizzle
    const float4* wt4 = reinterpret_cast<const float4*>(g_wt);

    int cur_v = -1;
    float4 w0, w1, w2, w3;  // lane d's weight column W[v][lane][0..15]
    w0 = w1 = w2 = w3 = make_float4(0.f, 0.f, 0.f, 0.f);

    for (int base = wstart; base < wend; base += 32) {
        int cnt = min(32, wend - base);
        bool valid = (lane < cnt);

        uint2 pair = make_uint2(0u, 0u);
        if (valid) pair = g_spair[base + lane];

        // Basis for ray = lane (garbage for invalid lanes is never read).
        float t = __uint_as_float(pair.x);
        float bb[16];
        bb[0] = 1.0f;
        float s, c;
        sincospif(t, &s, &c);
#pragma unroll
        for (int j = 0; j < EMB_F; j++) {
            bb[1 + j] = s;
            bb[1 + EMB_F + j] = c;
            float s2 = 2.0f * s * c;
            float c2 = fmaf(c, c, -s * s);
            s = s2;
            c = c2;
        }
        bb[13] = bb[14] = bb[15] = 0.0f;

        // Stage basis row: logical quad j at physical quad j ^ sl.
        float4* row = reinterpret_cast<float4*>(sb + lane * 16);
        row[0 ^ sl] = make_float4(bb[0], bb[1], bb[2], bb[3]);
        row[1 ^ sl] = make_float4(bb[4], bb[5], bb[6], bb[7]);
        row[2 ^ sl] = make_float4(bb[8], bb[9], bb[10], bb[11]);
        row[3 ^ sl] = make_float4(bb[12], 0.f, 0.f, 0.f);
        __syncwarp();

        // Dot phase: ray r at a time; all 32 lanes compute out[r][lane].
#pragma unroll 4
        for (int r = 0; r < cnt; r++) {
            unsigned pk = __shfl_sync(0xffffffffu, pair.y, r);
            int v = (int)(pk >> 26);
            if (v != cur_v) {  // warp-uniform; rare after first tile
                const float4* wp = wt4 + (v * EMB_D + lane) * 4;
                w0 = wp[0 ^ sl];
                w1 = wp[1 ^ sl];
                w2 = wp[2 ^ sl];
                w3 = wp[3 ^ sl];
                cur_v = v;
            }
            int sr = (r >> 1) & 3;
            const float4* brow = reinterpret_cast<const float4*>(sb + r * 16);
            float4 b0 = brow[0 ^ sr];   // broadcast
            float4 b1 = brow[1 ^ sr];
            float4 b2 = brow[2 ^ sr];
            float b12 = sb[r * 16 + ((3 ^ sr) << 2)];

            float acc = b0.x * w0.x;
            acc = fmaf(b0.y, w0.y, acc);
            acc = fmaf(b0.z, w0.z, acc);
            acc = fmaf(b0.w, w0.w, acc);
            acc = fmaf(b1.x, w1.x, acc);
            acc = fmaf(b1.y, w1.y, acc);
            acc = fmaf(b1.z, w1.z, acc);
            acc = fmaf(b1.w, w1.w, acc);
            acc = fmaf(b2.x, w2.x, acc);
            acc = fmaf(b2.y, w2.y, acc);
            acc = fmaf(b2.z, w2.z, acc);
            acc = fmaf(b2.w, w2.w, acc);
            acc = fmaf(b12, w3.x, acc);

            unsigned idx = pk & ((1u << 26) - 1u);
            out[((size_t)idx << 5) + lane] = acc;  // full 128B row, coalesced
        }
        __syncwarp();
    }
}

extern "C" void kernel_launch(void* const* d_in, const int* in_sizes, int n_in,
                              void* d_out, int out_size) {
    const float* times = (const float*)d_in[0];
    const int* vids = (const int*)d_in[1];
    const float* weights = (const float*)d_in[2];
    float* out = (float*)d_out;

    int n = in_sizes[0];
    if (n > NMAX) n = NMAX;  // problem size is 1M; scratch capacity guard

    transpose_weights_kernel<<<(EMB_V * EMB_D * 16 + 255) / 256, 256>>>(weights);
    hist_kernel<<<HIST_GRID, 256>>>(vids, n);
    scan_kernel<<<1, 32>>>();
    scatter_kernel<<<SC_BLOCKS, 256>>>(times, vids, n);
    main_kernel<<<MAIN_GRID, MAIN_THREADS>>>(out, n);
}